// round 10
// baseline (speedup 1.0000x reference)
#include <cuda_runtime.h>
#include <cstdint>
#include <math.h>

// Problem constants
constexpr int B_   = 16;
constexpr int H_   = 16;
constexpr int HD_  = 128;
constexpr int D_   = 2048;
constexpr int SPAST = 4096;
constexpr int SPLITS = 8;
constexpr int CHUNK  = 512;   // SPAST / SPLITS
constexpr float SCALING = 0.08838834764831845f;  // 128^-0.5

// GEMV tiling
constexpr int TILE_O   = 16;    // output rows per block
constexpr int TILE_D4  = 32;    // float4s per chunk = 128 dims
constexpr int STAGES   = 5;     // weight pipeline depth
constexpr int GKSPLIT  = 4;     // split-K factor
constexpr int NCHUNK   = 16 / GKSPLIT;               // chunks per block (4)
constexpr int SW_F4    = STAGES * TILE_O * TILE_D4;  // 2560 float4 = 40 KB
constexpr int SX_F4    = 16 * NCHUNK * TILE_D4;      // 2048 float4 = 32 KB
constexpr int GEMV_SMEM = (SW_F4 + SX_F4) * 16;      // 73728 bytes

// Scratch (static device globals — no allocation allowed)
__device__ float g_q[B_ * D_];
__device__ float g_attn[B_ * D_];
__device__ float g_pm[B_ * H_ * SPLITS];
__device__ float g_pl[B_ * H_ * SPLITS];
__device__ float g_pacc[B_ * H_ * SPLITS * HD_];

struct GemvArgs {
    const float* W[3];
    float*       out[3];
    float        scale[3];
};

__device__ __forceinline__ void cp_async16(unsigned int saddr, const void* g) {
    asm volatile("cp.async.cg.shared.global [%0], [%1], 16;" :: "r"(saddr), "l"(g));
}
__device__ __forceinline__ void cp_commit() {
    asm volatile("cp.async.commit_group;");
}
__device__ __forceinline__ void cp_wait3() {
    asm volatile("cp.async.wait_group 3;");  // STAGES-2
}

// ---------------------------------------------------------------------------
// Seed q/knew/vnew with bias so the split-K QKV gemv can pure-atomicAdd.
// (out is seeded by attn_combine_kernel.)
// ---------------------------------------------------------------------------
__global__ __launch_bounds__(256) void init_kernel(
    float* q, float* knew, float* vnew,
    const float* __restrict__ bq, const float* __restrict__ bk,
    const float* __restrict__ bv) {
    int idx = blockIdx.x * 256 + threadIdx.x;   // [0, 32768)
    int o = idx & (D_ - 1);
    q[idx]    = bq[o] * SCALING;
    knew[idx] = bk[o];
    vnew[idx] = bv[o];
}

// ---------------------------------------------------------------------------
// All-smem split-K GEMV. Two lessons baked in:
//   r6: the inner loop serializes if per-thread global x-loads can't batch.
//   r9: weight bytes must be in flight in smem (cp.async), not registers.
// So: the block's x slice (16 batches x 4 chunks = 32 KB) is loaded ONCE into
// smem in cp.async group 0; weights stream through a 5-stage 8KB pipeline.
// Inner loop is pure LDS+FFMA (short-scoreboard, hidden by 24 warps/SM).
// 256 threads; warp owns 2 rows x 16 batches; atomicAdd into bias-preseeded
// outputs. Dynamic smem = 72 KB -> 3 blocks/SM.
// ---------------------------------------------------------------------------
__global__ __launch_bounds__(256) void gemv_kernel(const float* __restrict__ x,
                                                   GemvArgs a) {
    extern __shared__ float4 smem[];
    float4* sw = smem;            // [STAGES][TILE_O][TILE_D4]
    float4* sx = smem + SW_F4;    // [16][NCHUNK*TILE_D4]

    int tid  = threadIdx.x;
    int warp = tid >> 5;
    int lane = tid & 31;
    int row0 = blockIdx.x * TILE_O;
    int mi   = row0 >> 11;        // which matrix (2048 rows each)
    int o0   = row0 & 2047;

    const float4* W = (const float4*)a.W[mi];
    const float4* X = (const float4*)x;

    const int c0 = blockIdx.y * NCHUNK;   // starting chunk (128 dims each)

    // Weight loader: thread t covers float4 #t and #(t+256) of 512 per stage.
    auto issue_w = [&](int c, int stage) {
#pragma unroll
        for (int k = 0; k < 2; k++) {
            int fi = tid + k * 256;
            int r  = fi >> 5;
            int d4 = fi & 31;
            unsigned int sa = (unsigned int)__cvta_generic_to_shared(
                &sw[stage * (TILE_O * TILE_D4) + r * TILE_D4 + d4]);
            cp_async16(sa, &W[(size_t)(o0 + r) * 512 + (size_t)(c0 + c) * TILE_D4 + d4]);
        }
    };

    // x loader: 2048 float4 (16 batches x 128 dim4), 8 per thread.
    {
#pragma unroll
        for (int k = 0; k < 8; k++) {
            int fi = tid + k * 256;
            int b  = fi >> 7;          // batch
            int r  = fi & 127;         // dim4 within the block's 512-dim slice
            unsigned int sa = (unsigned int)__cvta_generic_to_shared(
                &sx[b * (NCHUNK * TILE_D4) + r]);
            cp_async16(sa, &X[b * 512 + c0 * TILE_D4 + r]);
        }
    }

    float acc[2][16];
#pragma unroll
    for (int r = 0; r < 2; r++)
#pragma unroll
        for (int b = 0; b < 16; b++) acc[r][b] = 0.f;

    // Prologue: group 0 = x + weight chunk 0; groups 1..3 = chunks 1..3.
    issue_w(0, 0);
    cp_commit();
#pragma unroll
    for (int c = 1; c < STAGES - 1; c++) {
        if (c < NCHUNK) issue_w(c, c);
        cp_commit();
    }

    const int r0 = warp * 2;
#pragma unroll
    for (int c = 0; c < NCHUNK; c++) {
        cp_wait3();
        __syncthreads();   // chunk c (and x) resident; prev compute done
        int st = (c % STAGES) * (TILE_O * TILE_D4);
        float4 w0 = sw[st + (r0 + 0) * TILE_D4 + lane];
        float4 w1 = sw[st + (r0 + 1) * TILE_D4 + lane];
#pragma unroll
        for (int b = 0; b < 16; b++) {
            float4 xv = sx[b * (NCHUNK * TILE_D4) + c * TILE_D4 + lane];
            acc[0][b] += w0.x * xv.x + w0.y * xv.y + w0.z * xv.z + w0.w * xv.w;
            acc[1][b] += w1.x * xv.x + w1.y * xv.y + w1.z * xv.z + w1.w * xv.w;
        }
        int cn = c + STAGES - 1;
        if (cn < NCHUNK) issue_w(cn, cn % STAGES);
        cp_commit();       // empty tail groups keep accounting aligned
    }

    // Warp-reduce the 32 partial sums.
#pragma unroll
    for (int r = 0; r < 2; r++)
#pragma unroll
        for (int b = 0; b < 16; b++) {
            float v = acc[r][b];
            v += __shfl_xor_sync(0xffffffffu, v, 16);
            v += __shfl_xor_sync(0xffffffffu, v, 8);
            v += __shfl_xor_sync(0xffffffffu, v, 4);
            v += __shfl_xor_sync(0xffffffffu, v, 2);
            v += __shfl_xor_sync(0xffffffffu, v, 1);
            acc[r][b] = v;
        }

    float* out = a.out[mi];
    float  sc  = a.scale[mi];
#pragma unroll
    for (int r = 0; r < 2; r++)
#pragma unroll
        for (int b = 0; b < 16; b++)
            if (lane == b)
                atomicAdd(&out[b * D_ + o0 + r0 + r], acc[r][b] * sc);
}

// ---------------------------------------------------------------------------
// Split-S flash-decode attention partials (proven structure, untouched).
// grid = (256 bh, 8 splits), block = 256 (8 warps). Warp-per-row online
// softmax; each lane owns 4 head-dim elements (float4).
// K/V are a 1 GB single-use stream: __ldcs keeps them out of L2's way.
// ---------------------------------------------------------------------------
__global__ __launch_bounds__(256) void attn_partial_kernel(
    const float* __restrict__ pk, const float* __restrict__ pv,
    const float* __restrict__ mask,
    const float* __restrict__ knew, const float* __restrict__ vnew) {
    int bh    = blockIdx.x;
    int split = blockIdx.y;
    int b     = bh >> 4;
    int h     = bh & 15;
    int warp  = threadIdx.x >> 5;
    int lane  = threadIdx.x & 31;

    const float4* q4p = (const float4*)(g_q + b * D_ + h * HD_);
    float4 q4 = q4p[lane];  // q pre-scaled by SCALING

    size_t base = ((size_t)b * SPAST) * D_ + h * HD_;

    float  m = -1e30f, l = 0.f;
    float4 acc = make_float4(0.f, 0.f, 0.f, 0.f);

    int s0 = split * CHUNK + warp;
    int s_end = split * CHUNK + CHUNK;

#pragma unroll 4
    for (int s = s0; s < s_end; s += 8) {
        const float4* kr = (const float4*)(pk + base + (size_t)s * D_);
        const float4* vr = (const float4*)(pv + base + (size_t)s * D_);
        float4 k4 = __ldcs(&kr[lane]);
        float4 v4 = __ldcs(&vr[lane]);
        float sc = k4.x * q4.x + k4.y * q4.y + k4.z * q4.z + k4.w * q4.w;
        sc += __shfl_xor_sync(0xffffffffu, sc, 16);
        sc += __shfl_xor_sync(0xffffffffu, sc, 8);
        sc += __shfl_xor_sync(0xffffffffu, sc, 4);
        sc += __shfl_xor_sync(0xffffffffu, sc, 2);
        sc += __shfl_xor_sync(0xffffffffu, sc, 1);
        sc += mask[s];
        float nm   = fmaxf(m, sc);
        float corr = __expf(m - nm);
        float p    = __expf(sc - nm);
        m = nm;
        l = l * corr + p;
        acc.x = acc.x * corr + p * v4.x;
        acc.y = acc.y * corr + p * v4.y;
        acc.z = acc.z * corr + p * v4.z;
        acc.w = acc.w * corr + p * v4.w;
    }

    // The new token (s = 4096) lives in the last split, handled by warp 0.
    if (split == SPLITS - 1 && warp == 0) {
        const float4* kr = (const float4*)(knew + b * D_ + h * HD_);
        const float4* vr = (const float4*)(vnew + b * D_ + h * HD_);
        float4 k4 = kr[lane];
        float4 v4 = vr[lane];
        float sc = k4.x * q4.x + k4.y * q4.y + k4.z * q4.z + k4.w * q4.w;
        sc += __shfl_xor_sync(0xffffffffu, sc, 16);
        sc += __shfl_xor_sync(0xffffffffu, sc, 8);
        sc += __shfl_xor_sync(0xffffffffu, sc, 4);
        sc += __shfl_xor_sync(0xffffffffu, sc, 2);
        sc += __shfl_xor_sync(0xffffffffu, sc, 1);
        sc += mask[SPAST];
        float nm   = fmaxf(m, sc);
        float corr = __expf(m - nm);
        float p    = __expf(sc - nm);
        m = nm;
        l = l * corr + p;
        acc.x = acc.x * corr + p * v4.x;
        acc.y = acc.y * corr + p * v4.y;
        acc.z = acc.z * corr + p * v4.z;
        acc.w = acc.w * corr + p * v4.w;
    }

    // Combine the 8 warps of this block.
    __shared__ float  sm_m[8], sm_l[8];
    __shared__ float4 sm_acc[8][32];
    sm_acc[warp][lane] = acc;
    if (lane == 0) { sm_m[warp] = m; sm_l[warp] = l; }
    __syncthreads();

    if (threadIdx.x < HD_) {
        int d = threadIdx.x;
        float M = -1e30f;
#pragma unroll
        for (int w = 0; w < 8; w++) M = fmaxf(M, sm_m[w]);
        float L = 0.f, A = 0.f;
        const float* accf = (const float*)sm_acc;
#pragma unroll
        for (int w = 0; w < 8; w++) {
            float e = __expf(sm_m[w] - M);
            L += sm_l[w] * e;
            A += accf[w * HD_ + d] * e;
        }
        int idx = bh * SPLITS + split;
        g_pacc[idx * HD_ + d] = A;
        if (d == 0) { g_pm[idx] = M; g_pl[idx] = L; }
    }
}

// ---------------------------------------------------------------------------
// Combine the 8 split partials per (b,h) AND seed the final output buffer
// with the Wo bias, so the Wo split-K gemv can pure-atomicAdd.
// ---------------------------------------------------------------------------
__global__ __launch_bounds__(128) void attn_combine_kernel(
    float* __restrict__ out, const float* __restrict__ bo) {
    int bh = blockIdx.x;
    int d  = threadIdx.x;

    int oidx = bh * HD_ + d;          // [0, 32768)
    out[oidx] = bo[oidx & (D_ - 1)];  // seed Wo bias

    float M = -1e30f;
#pragma unroll
    for (int i = 0; i < SPLITS; i++) M = fmaxf(M, g_pm[bh * SPLITS + i]);
    float L = 0.f, A = 0.f;
#pragma unroll
    for (int i = 0; i < SPLITS; i++) {
        float e = __expf(g_pm[bh * SPLITS + i] - M);
        L += g_pl[bh * SPLITS + i] * e;
        A += g_pacc[(bh * SPLITS + i) * HD_ + d] * e;
    }
    int b = bh >> 4, h = bh & 15;
    g_attn[b * D_ + h * HD_ + d] = A / L;
}

// ---------------------------------------------------------------------------
extern "C" void kernel_launch(void* const* d_in, const int* in_sizes, int n_in,
                              void* d_out, int out_size) {
    const float* hs   = (const float*)d_in[0];
    const float* pk   = (const float*)d_in[1];
    const float* pv   = (const float*)d_in[2];
    const float* mask = (const float*)d_in[3];
    const float* Wq   = (const float*)d_in[4];
    const float* bq   = (const float*)d_in[5];
    const float* Wk   = (const float*)d_in[6];
    const float* bk   = (const float*)d_in[7];
    const float* Wv   = (const float*)d_in[8];
    const float* bv   = (const float*)d_in[9];
    const float* Wo   = (const float*)d_in[10];
    const float* bo   = (const float*)d_in[11];

    float* out  = (float*)d_out;          // [0, 32768): attn_output
    float* knew = out + B_ * D_;          // [32768, 65536): new_key
    float* vnew = out + 2 * B_ * D_;      // [65536, 98304): new_value

    float* qptr;  cudaGetSymbolAddress((void**)&qptr, g_q);
    float* aptr;  cudaGetSymbolAddress((void**)&aptr, g_attn);

    static bool attr_set = false;
    if (!attr_set) {
        cudaFuncSetAttribute(gemv_kernel,
                             cudaFuncAttributeMaxDynamicSharedMemorySize,
                             GEMV_SMEM);
        attr_set = true;
    }

    // 1. Seed q/knew/vnew with bias.
    init_kernel<<<128, 256>>>(qptr, knew, vnew, bq, bk, bv);

    // 2. Fused split-K QKV projection: 384 x-blocks * 4 k-splits.
    GemvArgs a;
    a.W[0] = Wq; a.out[0] = qptr; a.scale[0] = SCALING;
    a.W[1] = Wk; a.out[1] = knew; a.scale[1] = 1.f;
    a.W[2] = Wv; a.out[2] = vnew; a.scale[2] = 1.f;
    gemv_kernel<<<dim3(384, GKSPLIT), 256, GEMV_SMEM>>>(hs, a);

    // 3. Split-S attention partials (the HBM-bound 1.07 GB stream).
    attn_partial_kernel<<<dim3(B_ * H_, SPLITS), 256>>>(pk, pv, mask, knew, vnew);

    // 4. Combine partials + seed out with Wo bias.
    attn_combine_kernel<<<B_ * H_, 128>>>(out, bo);

    // 5. Output projection: 128 x-blocks * 4 k-splits.
    GemvArgs ao;
    ao.W[0] = Wo; ao.out[0] = out; ao.scale[0] = 1.f;
    ao.W[1] = Wo; ao.out[1] = out; ao.scale[1] = 1.f;
    ao.W[2] = Wo; ao.out[2] = out; ao.scale[2] = 1.f;
    gemv_kernel<<<dim3(128, GKSPLIT), 256, GEMV_SMEM>>>(aptr, ao);
}

// round 11
// speedup vs baseline: 1.0026x; 1.0026x over previous
#include <cuda_runtime.h>
#include <cstdint>
#include <math.h>

// Problem constants
constexpr int B_   = 16;
constexpr int H_   = 16;
constexpr int HD_  = 128;
constexpr int D_   = 2048;
constexpr int SPAST = 4096;
constexpr int SPLITS = 8;
constexpr int CHUNK  = 512;   // SPAST / SPLITS
constexpr float SCALING = 0.08838834764831845f;  // 128^-0.5

// Scratch (static device globals — no allocation allowed)
__device__ float g_q[B_ * D_];
__device__ float g_attn[B_ * D_];
__device__ float g_pm[B_ * H_ * SPLITS];
__device__ float g_pl[B_ * H_ * SPLITS];
__device__ float g_pacc[B_ * H_ * SPLITS * HD_];

struct GemvArgs {
    const float* W[3];
    const float* bias[3];
    float*       out[3];
    float        scale[3];
};

// ---------------------------------------------------------------------------
// Long-block GEMV: out[b,o] = (sum_d x[b,d]*W[o,d] + bias[o]) * scale.
// Evidence from r7: the SAME inner loop ran at 2.4 TB/s with 16-iteration
// blocks (QKV) but 0.51 TB/s with 4-iteration blocks (Wo split-K) — short
// blocks never amortize the ~600-cycle DRAM pipeline fill. So: every block
// covers the FULL 2048-dim reduction (16 iterations), and grid parallelism
// comes from 2 rows/warp (8 rows per 128-thread block) instead of split-K.
// 2 rows/warp also frees registers for prefetch depth 2 (64 B/lane in
// flight); ~75 regs -> ~6 blocks/SM -> ~24 warps -> ~49 KB/SM in flight.
// Direct bias store: no atomics, no init pass.
// ---------------------------------------------------------------------------
__global__ __launch_bounds__(128) void gemv_kernel(const float* __restrict__ x,
                                                   GemvArgs a) {
    int gw   = (blockIdx.x * 128 + threadIdx.x) >> 5;  // global warp id
    int lane = threadIdx.x & 31;
    int row0 = gw * 2;
    int mi   = row0 >> 11;      // which matrix (rows are 2048 per matrix)
    int o0   = row0 & 2047;

    const float4* W = (const float4*)a.W[mi];
    const float4* X = (const float4*)x;

    float acc[2][16];
#pragma unroll
    for (int r = 0; r < 2; r++)
#pragma unroll
        for (int b = 0; b < 16; b++) acc[r][b] = 0.f;

    // Prefetch depth 2: wbuf[parity][row].
    float4 wbuf[2][2];
    wbuf[0][0] = __ldcs(&W[(size_t)(o0 + 0) * 512 + lane]);
    wbuf[0][1] = __ldcs(&W[(size_t)(o0 + 1) * 512 + lane]);
    wbuf[1][0] = __ldcs(&W[(size_t)(o0 + 0) * 512 + 32 + lane]);
    wbuf[1][1] = __ldcs(&W[(size_t)(o0 + 1) * 512 + 32 + lane]);

#pragma unroll
    for (int ii = 0; ii < 16; ii++) {
        float4 c0 = wbuf[ii & 1][0];
        float4 c1 = wbuf[ii & 1][1];
        int dcur = ii * 32 + lane;
        if (ii + 2 < 16) {
            int dn = (ii + 2) * 32 + lane;
            wbuf[ii & 1][0] = __ldcs(&W[(size_t)(o0 + 0) * 512 + dn]);
            wbuf[ii & 1][1] = __ldcs(&W[(size_t)(o0 + 1) * 512 + dn]);
        }
#pragma unroll
        for (int b = 0; b < 16; b++) {
            float4 xv = X[b * 512 + dcur];
            acc[0][b] += c0.x * xv.x + c0.y * xv.y + c0.z * xv.z + c0.w * xv.w;
            acc[1][b] += c1.x * xv.x + c1.y * xv.y + c1.z * xv.z + c1.w * xv.w;
        }
    }

    // Warp-reduce the 32 partial sums.
#pragma unroll
    for (int r = 0; r < 2; r++)
#pragma unroll
        for (int b = 0; b < 16; b++) {
            float v = acc[r][b];
            v += __shfl_xor_sync(0xffffffffu, v, 16);
            v += __shfl_xor_sync(0xffffffffu, v, 8);
            v += __shfl_xor_sync(0xffffffffu, v, 4);
            v += __shfl_xor_sync(0xffffffffu, v, 2);
            v += __shfl_xor_sync(0xffffffffu, v, 1);
            acc[r][b] = v;
        }

    const float* bias = a.bias[mi];
    float*       out  = a.out[mi];
    float        sc   = a.scale[mi];
#pragma unroll
    for (int r = 0; r < 2; r++) {
        float bb = bias[o0 + r];
#pragma unroll
        for (int b = 0; b < 16; b++)
            if (lane == b)
                out[b * D_ + o0 + r] = (acc[r][b] + bb) * sc;
    }
}

// ---------------------------------------------------------------------------
// Split-S flash-decode attention partials (proven structure, untouched).
// grid = (256 bh, 8 splits), block = 256 (8 warps). Warp-per-row online
// softmax; each lane owns 4 head-dim elements (float4).
// K/V are a 1 GB single-use stream: __ldcs keeps them out of L2's way.
// ---------------------------------------------------------------------------
__global__ __launch_bounds__(256) void attn_partial_kernel(
    const float* __restrict__ pk, const float* __restrict__ pv,
    const float* __restrict__ mask,
    const float* __restrict__ knew, const float* __restrict__ vnew) {
    int bh    = blockIdx.x;
    int split = blockIdx.y;
    int b     = bh >> 4;
    int h     = bh & 15;
    int warp  = threadIdx.x >> 5;
    int lane  = threadIdx.x & 31;

    const float4* q4p = (const float4*)(g_q + b * D_ + h * HD_);
    float4 q4 = q4p[lane];  // q pre-scaled by SCALING

    size_t base = ((size_t)b * SPAST) * D_ + h * HD_;

    float  m = -1e30f, l = 0.f;
    float4 acc = make_float4(0.f, 0.f, 0.f, 0.f);

    int s0 = split * CHUNK + warp;
    int s_end = split * CHUNK + CHUNK;

#pragma unroll 4
    for (int s = s0; s < s_end; s += 8) {
        const float4* kr = (const float4*)(pk + base + (size_t)s * D_);
        const float4* vr = (const float4*)(pv + base + (size_t)s * D_);
        float4 k4 = __ldcs(&kr[lane]);
        float4 v4 = __ldcs(&vr[lane]);
        float sc = k4.x * q4.x + k4.y * q4.y + k4.z * q4.z + k4.w * q4.w;
        sc += __shfl_xor_sync(0xffffffffu, sc, 16);
        sc += __shfl_xor_sync(0xffffffffu, sc, 8);
        sc += __shfl_xor_sync(0xffffffffu, sc, 4);
        sc += __shfl_xor_sync(0xffffffffu, sc, 2);
        sc += __shfl_xor_sync(0xffffffffu, sc, 1);
        sc += mask[s];
        float nm   = fmaxf(m, sc);
        float corr = __expf(m - nm);
        float p    = __expf(sc - nm);
        m = nm;
        l = l * corr + p;
        acc.x = acc.x * corr + p * v4.x;
        acc.y = acc.y * corr + p * v4.y;
        acc.z = acc.z * corr + p * v4.z;
        acc.w = acc.w * corr + p * v4.w;
    }

    // The new token (s = 4096) lives in the last split, handled by warp 0.
    if (split == SPLITS - 1 && warp == 0) {
        const float4* kr = (const float4*)(knew + b * D_ + h * HD_);
        const float4* vr = (const float4*)(vnew + b * D_ + h * HD_);
        float4 k4 = kr[lane];
        float4 v4 = vr[lane];
        float sc = k4.x * q4.x + k4.y * q4.y + k4.z * q4.z + k4.w * q4.w;
        sc += __shfl_xor_sync(0xffffffffu, sc, 16);
        sc += __shfl_xor_sync(0xffffffffu, sc, 8);
        sc += __shfl_xor_sync(0xffffffffu, sc, 4);
        sc += __shfl_xor_sync(0xffffffffu, sc, 2);
        sc += __shfl_xor_sync(0xffffffffu, sc, 1);
        sc += mask[SPAST];
        float nm   = fmaxf(m, sc);
        float corr = __expf(m - nm);
        float p    = __expf(sc - nm);
        m = nm;
        l = l * corr + p;
        acc.x = acc.x * corr + p * v4.x;
        acc.y = acc.y * corr + p * v4.y;
        acc.z = acc.z * corr + p * v4.z;
        acc.w = acc.w * corr + p * v4.w;
    }

    // Combine the 8 warps of this block.
    __shared__ float  sm_m[8], sm_l[8];
    __shared__ float4 sm_acc[8][32];
    sm_acc[warp][lane] = acc;
    if (lane == 0) { sm_m[warp] = m; sm_l[warp] = l; }
    __syncthreads();

    if (threadIdx.x < HD_) {
        int d = threadIdx.x;
        float M = -1e30f;
#pragma unroll
        for (int w = 0; w < 8; w++) M = fmaxf(M, sm_m[w]);
        float L = 0.f, A = 0.f;
        const float* accf = (const float*)sm_acc;
#pragma unroll
        for (int w = 0; w < 8; w++) {
            float e = __expf(sm_m[w] - M);
            L += sm_l[w] * e;
            A += accf[w * HD_ + d] * e;
        }
        int idx = bh * SPLITS + split;
        g_pacc[idx * HD_ + d] = A;
        if (d == 0) { g_pm[idx] = M; g_pl[idx] = L; }
    }
}

// ---------------------------------------------------------------------------
// Combine the 8 split partials per (b,h) into the attention output vector.
// ---------------------------------------------------------------------------
__global__ __launch_bounds__(128) void attn_combine_kernel() {
    int bh = blockIdx.x;
    int d  = threadIdx.x;
    float M = -1e30f;
#pragma unroll
    for (int i = 0; i < SPLITS; i++) M = fmaxf(M, g_pm[bh * SPLITS + i]);
    float L = 0.f, A = 0.f;
#pragma unroll
    for (int i = 0; i < SPLITS; i++) {
        float e = __expf(g_pm[bh * SPLITS + i] - M);
        L += g_pl[bh * SPLITS + i] * e;
        A += g_pacc[(bh * SPLITS + i) * HD_ + d] * e;
    }
    int b = bh >> 4, h = bh & 15;
    g_attn[b * D_ + h * HD_ + d] = A / L;
}

// ---------------------------------------------------------------------------
extern "C" void kernel_launch(void* const* d_in, const int* in_sizes, int n_in,
                              void* d_out, int out_size) {
    const float* hs   = (const float*)d_in[0];
    const float* pk   = (const float*)d_in[1];
    const float* pv   = (const float*)d_in[2];
    const float* mask = (const float*)d_in[3];
    const float* Wq   = (const float*)d_in[4];
    const float* bq   = (const float*)d_in[5];
    const float* Wk   = (const float*)d_in[6];
    const float* bk   = (const float*)d_in[7];
    const float* Wv   = (const float*)d_in[8];
    const float* bv   = (const float*)d_in[9];
    const float* Wo   = (const float*)d_in[10];
    const float* bo   = (const float*)d_in[11];

    float* out  = (float*)d_out;          // [0, 32768): attn_output
    float* knew = out + B_ * D_;          // [32768, 65536): new_key
    float* vnew = out + 2 * B_ * D_;      // [65536, 98304): new_value

    float* qptr;  cudaGetSymbolAddress((void**)&qptr, g_q);
    float* aptr;  cudaGetSymbolAddress((void**)&aptr, g_attn);

    // 1. Fused QKV projection: 6144 rows / 8 rows-per-block = 768 blocks,
    //    full-length reduction per block, direct bias store.
    GemvArgs a;
    a.W[0] = Wq; a.bias[0] = bq; a.out[0] = qptr; a.scale[0] = SCALING;
    a.W[1] = Wk; a.bias[1] = bk; a.out[1] = knew; a.scale[1] = 1.f;
    a.W[2] = Wv; a.bias[2] = bv; a.out[2] = vnew; a.scale[2] = 1.f;
    gemv_kernel<<<768, 128>>>(hs, a);

    // 2. Split-S attention partials (the HBM-bound 1.07 GB stream).
    attn_partial_kernel<<<dim3(B_ * H_, SPLITS), 256>>>(pk, pv, mask, knew, vnew);

    // 3. Combine partials.
    attn_combine_kernel<<<B_ * H_, 128>>>();

    // 4. Output projection: 2048 rows / 8 = 256 full-length blocks.
    GemvArgs ao;
    ao.W[0] = Wo; ao.bias[0] = bo; ao.out[0] = out; ao.scale[0] = 1.f;
    ao.W[1] = Wo; ao.bias[1] = bo; ao.out[1] = out; ao.scale[1] = 1.f;
    ao.W[2] = Wo; ao.bias[2] = bo; ao.out[2] = out; ao.scale[2] = 1.f;
    gemv_kernel<<<256, 128>>>(aptr, ao);
}

// round 12
// speedup vs baseline: 1.0138x; 1.0112x over previous
#include <cuda_runtime.h>
#include <cstdint>
#include <math.h>

// Problem constants
constexpr int B_   = 16;
constexpr int H_   = 16;
constexpr int HD_  = 128;
constexpr int D_   = 2048;
constexpr int SPAST = 4096;
constexpr int SPLITS = 8;
constexpr int CHUNK  = 512;   // SPAST / SPLITS
constexpr float SCALING = 0.08838834764831845f;  // 128^-0.5

// Scratch (static device globals — no allocation allowed)
__device__ float g_q[B_ * D_];
__device__ float g_attn[B_ * D_];
__device__ float g_pm[B_ * H_ * SPLITS];
__device__ float g_pl[B_ * H_ * SPLITS];
__device__ float g_pacc[B_ * H_ * SPLITS * HD_];

struct GemvArgs {
    const float* W[3];
    float*       out[3];
    float        scale[3];
};

// ---------------------------------------------------------------------------
// Seed q/knew/vnew with bias so the split-K QKV gemv can pure-atomicAdd.
// (out is seeded by attn_combine_kernel.)
// ---------------------------------------------------------------------------
__global__ __launch_bounds__(256) void init_kernel(
    float* q, float* knew, float* vnew,
    const float* __restrict__ bq, const float* __restrict__ bk,
    const float* __restrict__ bv) {
    int idx = blockIdx.x * 256 + threadIdx.x;   // [0, 32768)
    int o = idx & (D_ - 1);
    q[idx]    = bq[o] * SCALING;
    knew[idx] = bk[o];
    vnew[idx] = bv[o];
}

// ---------------------------------------------------------------------------
// Warp-maximized split-K GEMV.
// Empirical law from rounds 4/7/11: gemv bandwidth ~= 42 GB/s per resident
// warp per SM — nothing else (block length, f32x2, cp.async depth) moved it.
// So this version minimizes registers per warp (2 rows -> acc = 32 regs,
// depth-1 prefetch) to fit 4 x 256-thread blocks per SM (32 warps), and uses
// split-K only to supply enough blocks. atomicAdd into bias-preseeded output.
// ---------------------------------------------------------------------------
template <int KSPLIT>
__global__ __launch_bounds__(256) void gemv_kernel(const float* __restrict__ x,
                                                   GemvArgs a) {
    int gw   = (blockIdx.x * 256 + threadIdx.x) >> 5;  // global warp id
    int lane = threadIdx.x & 31;
    int row0 = gw * 2;
    int mi   = row0 >> 11;      // which matrix (rows are 2048 per matrix)
    int o0   = row0 & 2047;

    const float4* W = (const float4*)a.W[mi];
    const float4* X = (const float4*)x;

    float acc[2][16];
#pragma unroll
    for (int r = 0; r < 2; r++)
#pragma unroll
        for (int b = 0; b < 16; b++) acc[r][b] = 0.f;

    constexpr int ITERS = 16 / KSPLIT;
    int i0 = blockIdx.y * ITERS;

    // Depth-1 prefetch of the two weight rows.
    int d4 = i0 * 32 + lane;
    float4 w0 = __ldcs(&W[(size_t)(o0 + 0) * 512 + d4]);
    float4 w1 = __ldcs(&W[(size_t)(o0 + 1) * 512 + d4]);

#pragma unroll
    for (int ii = 0; ii < ITERS; ii++) {
        float4 c0 = w0, c1 = w1;
        int dcur = d4;
        if (ii + 1 < ITERS) {
            d4 += 32;
            w0 = __ldcs(&W[(size_t)(o0 + 0) * 512 + d4]);
            w1 = __ldcs(&W[(size_t)(o0 + 1) * 512 + d4]);
        }
#pragma unroll
        for (int b = 0; b < 16; b++) {
            float4 xv = X[b * 512 + dcur];
            acc[0][b] += c0.x * xv.x + c0.y * xv.y + c0.z * xv.z + c0.w * xv.w;
            acc[1][b] += c1.x * xv.x + c1.y * xv.y + c1.z * xv.z + c1.w * xv.w;
        }
    }

    // Warp-reduce the 32 partial sums.
#pragma unroll
    for (int r = 0; r < 2; r++)
#pragma unroll
        for (int b = 0; b < 16; b++) {
            float v = acc[r][b];
            v += __shfl_xor_sync(0xffffffffu, v, 16);
            v += __shfl_xor_sync(0xffffffffu, v, 8);
            v += __shfl_xor_sync(0xffffffffu, v, 4);
            v += __shfl_xor_sync(0xffffffffu, v, 2);
            v += __shfl_xor_sync(0xffffffffu, v, 1);
            acc[r][b] = v;
        }

    float* out = a.out[mi];
    float  sc  = a.scale[mi];
#pragma unroll
    for (int r = 0; r < 2; r++)
#pragma unroll
        for (int b = 0; b < 16; b++)
            if (lane == b)
                atomicAdd(&out[b * D_ + o0 + r], acc[r][b] * sc);
}

// ---------------------------------------------------------------------------
// Split-S flash-decode attention partials (proven structure, untouched).
// grid = (256 bh, 8 splits), block = 256 (8 warps). Warp-per-row online
// softmax; each lane owns 4 head-dim elements (float4).
// K/V are a 1 GB single-use stream: __ldcs keeps them out of L2's way.
// ---------------------------------------------------------------------------
__global__ __launch_bounds__(256) void attn_partial_kernel(
    const float* __restrict__ pk, const float* __restrict__ pv,
    const float* __restrict__ mask,
    const float* __restrict__ knew, const float* __restrict__ vnew) {
    int bh    = blockIdx.x;
    int split = blockIdx.y;
    int b     = bh >> 4;
    int h     = bh & 15;
    int warp  = threadIdx.x >> 5;
    int lane  = threadIdx.x & 31;

    const float4* q4p = (const float4*)(g_q + b * D_ + h * HD_);
    float4 q4 = q4p[lane];  // q pre-scaled by SCALING

    size_t base = ((size_t)b * SPAST) * D_ + h * HD_;

    float  m = -1e30f, l = 0.f;
    float4 acc = make_float4(0.f, 0.f, 0.f, 0.f);

    int s0 = split * CHUNK + warp;
    int s_end = split * CHUNK + CHUNK;

#pragma unroll 4
    for (int s = s0; s < s_end; s += 8) {
        const float4* kr = (const float4*)(pk + base + (size_t)s * D_);
        const float4* vr = (const float4*)(pv + base + (size_t)s * D_);
        float4 k4 = __ldcs(&kr[lane]);
        float4 v4 = __ldcs(&vr[lane]);
        float sc = k4.x * q4.x + k4.y * q4.y + k4.z * q4.z + k4.w * q4.w;
        sc += __shfl_xor_sync(0xffffffffu, sc, 16);
        sc += __shfl_xor_sync(0xffffffffu, sc, 8);
        sc += __shfl_xor_sync(0xffffffffu, sc, 4);
        sc += __shfl_xor_sync(0xffffffffu, sc, 2);
        sc += __shfl_xor_sync(0xffffffffu, sc, 1);
        sc += mask[s];
        float nm   = fmaxf(m, sc);
        float corr = __expf(m - nm);
        float p    = __expf(sc - nm);
        m = nm;
        l = l * corr + p;
        acc.x = acc.x * corr + p * v4.x;
        acc.y = acc.y * corr + p * v4.y;
        acc.z = acc.z * corr + p * v4.z;
        acc.w = acc.w * corr + p * v4.w;
    }

    // The new token (s = 4096) lives in the last split, handled by warp 0.
    if (split == SPLITS - 1 && warp == 0) {
        const float4* kr = (const float4*)(knew + b * D_ + h * HD_);
        const float4* vr = (const float4*)(vnew + b * D_ + h * HD_);
        float4 k4 = kr[lane];
        float4 v4 = vr[lane];
        float sc = k4.x * q4.x + k4.y * q4.y + k4.z * q4.z + k4.w * q4.w;
        sc += __shfl_xor_sync(0xffffffffu, sc, 16);
        sc += __shfl_xor_sync(0xffffffffu, sc, 8);
        sc += __shfl_xor_sync(0xffffffffu, sc, 4);
        sc += __shfl_xor_sync(0xffffffffu, sc, 2);
        sc += __shfl_xor_sync(0xffffffffu, sc, 1);
        sc += mask[SPAST];
        float nm   = fmaxf(m, sc);
        float corr = __expf(m - nm);
        float p    = __expf(sc - nm);
        m = nm;
        l = l * corr + p;
        acc.x = acc.x * corr + p * v4.x;
        acc.y = acc.y * corr + p * v4.y;
        acc.z = acc.z * corr + p * v4.z;
        acc.w = acc.w * corr + p * v4.w;
    }

    // Combine the 8 warps of this block.
    __shared__ float  sm_m[8], sm_l[8];
    __shared__ float4 sm_acc[8][32];
    sm_acc[warp][lane] = acc;
    if (lane == 0) { sm_m[warp] = m; sm_l[warp] = l; }
    __syncthreads();

    if (threadIdx.x < HD_) {
        int d = threadIdx.x;
        float M = -1e30f;
#pragma unroll
        for (int w = 0; w < 8; w++) M = fmaxf(M, sm_m[w]);
        float L = 0.f, A = 0.f;
        const float* accf = (const float*)sm_acc;
#pragma unroll
        for (int w = 0; w < 8; w++) {
            float e = __expf(sm_m[w] - M);
            L += sm_l[w] * e;
            A += accf[w * HD_ + d] * e;
        }
        int idx = bh * SPLITS + split;
        g_pacc[idx * HD_ + d] = A;
        if (d == 0) { g_pm[idx] = M; g_pl[idx] = L; }
    }
}

// ---------------------------------------------------------------------------
// Combine the 8 split partials per (b,h) AND seed the final output buffer
// with the Wo bias, so the Wo split-K gemv can pure-atomicAdd.
// ---------------------------------------------------------------------------
__global__ __launch_bounds__(128) void attn_combine_kernel(
    float* __restrict__ out, const float* __restrict__ bo) {
    int bh = blockIdx.x;
    int d  = threadIdx.x;

    int oidx = bh * HD_ + d;          // [0, 32768)
    out[oidx] = bo[oidx & (D_ - 1)];  // seed Wo bias

    float M = -1e30f;
#pragma unroll
    for (int i = 0; i < SPLITS; i++) M = fmaxf(M, g_pm[bh * SPLITS + i]);
    float L = 0.f, A = 0.f;
#pragma unroll
    for (int i = 0; i < SPLITS; i++) {
        float e = __expf(g_pm[bh * SPLITS + i] - M);
        L += g_pl[bh * SPLITS + i] * e;
        A += g_pacc[(bh * SPLITS + i) * HD_ + d] * e;
    }
    int b = bh >> 4, h = bh & 15;
    g_attn[b * D_ + h * HD_ + d] = A / L;
}

// ---------------------------------------------------------------------------
extern "C" void kernel_launch(void* const* d_in, const int* in_sizes, int n_in,
                              void* d_out, int out_size) {
    const float* hs   = (const float*)d_in[0];
    const float* pk   = (const float*)d_in[1];
    const float* pv   = (const float*)d_in[2];
    const float* mask = (const float*)d_in[3];
    const float* Wq   = (const float*)d_in[4];
    const float* bq   = (const float*)d_in[5];
    const float* Wk   = (const float*)d_in[6];
    const float* bk   = (const float*)d_in[7];
    const float* Wv   = (const float*)d_in[8];
    const float* bv   = (const float*)d_in[9];
    const float* Wo   = (const float*)d_in[10];
    const float* bo   = (const float*)d_in[11];

    float* out  = (float*)d_out;          // [0, 32768): attn_output
    float* knew = out + B_ * D_;          // [32768, 65536): new_key
    float* vnew = out + 2 * B_ * D_;      // [65536, 98304): new_value

    float* qptr;  cudaGetSymbolAddress((void**)&qptr, g_q);
    float* aptr;  cudaGetSymbolAddress((void**)&aptr, g_attn);

    // 1. Seed q/knew/vnew with bias.
    init_kernel<<<128, 256>>>(qptr, knew, vnew, bq, bk, bv);

    // 2. Fused split-K QKV projection: 16 rows/block -> 384 x-blocks,
    //    KSPLIT=2 -> 768 blocks, ~41 warps/SM demanded (occ-capped ~32).
    GemvArgs a;
    a.W[0] = Wq; a.out[0] = qptr; a.scale[0] = SCALING;
    a.W[1] = Wk; a.out[1] = knew; a.scale[1] = 1.f;
    a.W[2] = Wv; a.out[2] = vnew; a.scale[2] = 1.f;
    gemv_kernel<2><<<dim3(384, 2), 256>>>(hs, a);

    // 3. Split-S attention partials (the HBM-bound 1.07 GB stream).
    attn_partial_kernel<<<dim3(B_ * H_, SPLITS), 256>>>(pk, pv, mask, knew, vnew);

    // 4. Combine partials + seed out with Wo bias.
    attn_combine_kernel<<<B_ * H_, 128>>>(out, bo);

    // 5. Output projection: 128 x-blocks, KSPLIT=4 -> 512 blocks (~27 warps/SM).
    GemvArgs ao;
    ao.W[0] = Wo; ao.out[0] = out; ao.scale[0] = 1.f;
    ao.W[1] = Wo; ao.out[1] = out; ao.scale[1] = 1.f;
    ao.W[2] = Wo; ao.out[2] = out; ao.scale[2] = 1.f;
    gemv_kernel<4><<<dim3(128, 4), 256>>>(aptr, ao);
}

// round 13
// speedup vs baseline: 1.1226x; 1.1073x over previous
#include <cuda_runtime.h>
#include <cstdint>
#include <math.h>

// Problem constants
constexpr int B_   = 16;
constexpr int H_   = 16;
constexpr int HD_  = 128;
constexpr int D_   = 2048;
constexpr int SPAST = 4096;
constexpr int SPLITS = 8;
constexpr int CHUNK  = 512;   // SPAST / SPLITS
constexpr float SCALING = 0.08838834764831845f;  // 128^-0.5

// Scratch (static device globals — no allocation allowed)
__device__ float g_q[B_ * D_];
__device__ float g_attn[B_ * D_];
__device__ float g_pm[B_ * H_ * SPLITS];
__device__ float g_pl[B_ * H_ * SPLITS];
__device__ float g_pacc[B_ * H_ * SPLITS * HD_];

struct GemvArgs {
    const float* W[3];
    const float* bias[3];
    float*       out[3];
    float        scale[3];
};

// ---------------------------------------------------------------------------
// r7 GEMV (the only config that ever measured fast) with ONE change: the
// 64-sum x 5-level SHFL warp reduction (~640 issue slots of 26-cycle
// dependent shuffles -- >50% of block time at small ITERS) is replaced by a
// padded-smem transpose reduction (~200 instrs, no long dependence chains).
// Geometry unchanged: 128 threads, 4 warps x 4 rows, depth-1 prefetch,
// KSPLIT=1 -> direct bias store; KSPLIT>1 -> atomicAdd into preseeded out.
// ---------------------------------------------------------------------------
template <int KSPLIT>
__global__ __launch_bounds__(128) void gemv_kernel(const float* __restrict__ x,
                                                   GemvArgs a) {
    __shared__ float sacc[256][33];   // 256 outputs x 32 lane-partials, pad 33

    int tid  = threadIdx.x;
    int warp = tid >> 5;
    int lane = tid & 31;
    int blk_row0 = blockIdx.x * 16;
    int mi   = blk_row0 >> 11;        // which matrix (2048 rows each)
    int o0b  = blk_row0 & 2047;       // block's first row within matrix
    int o0   = o0b + warp * 4;        // this warp's first row

    const float4* W = (const float4*)a.W[mi];
    const float4* X = (const float4*)x;

    float acc[4][16];
#pragma unroll
    for (int r = 0; r < 4; r++)
#pragma unroll
        for (int b = 0; b < 16; b++) acc[r][b] = 0.f;

    constexpr int ITERS = 16 / KSPLIT;
    int i0 = blockIdx.y * ITERS;

    // Depth-1 prefetch of the four weight rows.
    int d4 = i0 * 32 + lane;
    float4 w0 = __ldcs(&W[(size_t)(o0 + 0) * 512 + d4]);
    float4 w1 = __ldcs(&W[(size_t)(o0 + 1) * 512 + d4]);
    float4 w2 = __ldcs(&W[(size_t)(o0 + 2) * 512 + d4]);
    float4 w3 = __ldcs(&W[(size_t)(o0 + 3) * 512 + d4]);

#pragma unroll
    for (int ii = 0; ii < ITERS; ii++) {
        float4 c0 = w0, c1 = w1, c2 = w2, c3 = w3;
        int dcur = d4;
        if (ii + 1 < ITERS) {
            d4 += 32;
            w0 = __ldcs(&W[(size_t)(o0 + 0) * 512 + d4]);
            w1 = __ldcs(&W[(size_t)(o0 + 1) * 512 + d4]);
            w2 = __ldcs(&W[(size_t)(o0 + 2) * 512 + d4]);
            w3 = __ldcs(&W[(size_t)(o0 + 3) * 512 + d4]);
        }
#pragma unroll
        for (int b = 0; b < 16; b++) {
            float4 xv = X[b * 512 + dcur];
            acc[0][b] += c0.x * xv.x + c0.y * xv.y + c0.z * xv.z + c0.w * xv.w;
            acc[1][b] += c1.x * xv.x + c1.y * xv.y + c1.z * xv.z + c1.w * xv.w;
            acc[2][b] += c2.x * xv.x + c2.y * xv.y + c2.z * xv.z + c2.w * xv.w;
            acc[3][b] += c3.x * xv.x + c3.y * xv.y + c3.z * xv.z + c3.w * xv.w;
        }
    }

    // ---- smem transpose reduction (replaces 64 x 5-shfl butterflies) ----
    // Store: lane-partial of output (warp, r, b) at sacc[warp*64+r*16+b][lane]
    // (consecutive lanes -> consecutive words -> conflict-free).
#pragma unroll
    for (int r = 0; r < 4; r++)
#pragma unroll
        for (int b = 0; b < 16; b++)
            sacc[warp * 64 + r * 16 + b][lane] = acc[r][b];
    __syncthreads();

    // Read: thread t sums the 32 lane-partials of outputs t and t+128.
    // Word index = out*33 + l -> bank (out+l)%32: conflict-free.
    const float* bias = a.bias[mi];
    float*       out  = a.out[mi];
    float        sc   = a.scale[mi];
#pragma unroll
    for (int k = 0; k < 2; k++) {
        int oidx = tid + k * 128;               // [0, 256)
        int w2 = oidx >> 6;
        int r2 = (oidx >> 4) & 3;
        int b2 = oidx & 15;
        int row = o0b + w2 * 4 + r2;
        float sum = 0.f;
#pragma unroll
        for (int l = 0; l < 32; l++) sum += sacc[oidx][l];
        if (KSPLIT == 1)
            out[b2 * D_ + row] = (sum + bias[row]) * sc;
        else
            atomicAdd(&out[b2 * D_ + row], sum * sc);
    }
}

// ---------------------------------------------------------------------------
// Split-S flash-decode attention partials (proven structure, untouched).
// grid = (256 bh, 8 splits), block = 256 (8 warps). Warp-per-row online
// softmax; each lane owns 4 head-dim elements (float4).
// K/V are a 1 GB single-use stream: __ldcs keeps them out of L2's way.
// ---------------------------------------------------------------------------
__global__ __launch_bounds__(256) void attn_partial_kernel(
    const float* __restrict__ pk, const float* __restrict__ pv,
    const float* __restrict__ mask,
    const float* __restrict__ knew, const float* __restrict__ vnew) {
    int bh    = blockIdx.x;
    int split = blockIdx.y;
    int b     = bh >> 4;
    int h     = bh & 15;
    int warp  = threadIdx.x >> 5;
    int lane  = threadIdx.x & 31;

    const float4* q4p = (const float4*)(g_q + b * D_ + h * HD_);
    float4 q4 = q4p[lane];  // q pre-scaled by SCALING

    size_t base = ((size_t)b * SPAST) * D_ + h * HD_;

    float  m = -1e30f, l = 0.f;
    float4 acc = make_float4(0.f, 0.f, 0.f, 0.f);

    int s0 = split * CHUNK + warp;
    int s_end = split * CHUNK + CHUNK;

#pragma unroll 4
    for (int s = s0; s < s_end; s += 8) {
        const float4* kr = (const float4*)(pk + base + (size_t)s * D_);
        const float4* vr = (const float4*)(pv + base + (size_t)s * D_);
        float4 k4 = __ldcs(&kr[lane]);
        float4 v4 = __ldcs(&vr[lane]);
        float sc = k4.x * q4.x + k4.y * q4.y + k4.z * q4.z + k4.w * q4.w;
        sc += __shfl_xor_sync(0xffffffffu, sc, 16);
        sc += __shfl_xor_sync(0xffffffffu, sc, 8);
        sc += __shfl_xor_sync(0xffffffffu, sc, 4);
        sc += __shfl_xor_sync(0xffffffffu, sc, 2);
        sc += __shfl_xor_sync(0xffffffffu, sc, 1);
        sc += mask[s];
        float nm   = fmaxf(m, sc);
        float corr = __expf(m - nm);
        float p    = __expf(sc - nm);
        m = nm;
        l = l * corr + p;
        acc.x = acc.x * corr + p * v4.x;
        acc.y = acc.y * corr + p * v4.y;
        acc.z = acc.z * corr + p * v4.z;
        acc.w = acc.w * corr + p * v4.w;
    }

    // The new token (s = 4096) lives in the last split, handled by warp 0.
    if (split == SPLITS - 1 && warp == 0) {
        const float4* kr = (const float4*)(knew + b * D_ + h * HD_);
        const float4* vr = (const float4*)(vnew + b * D_ + h * HD_);
        float4 k4 = kr[lane];
        float4 v4 = vr[lane];
        float sc = k4.x * q4.x + k4.y * q4.y + k4.z * q4.z + k4.w * q4.w;
        sc += __shfl_xor_sync(0xffffffffu, sc, 16);
        sc += __shfl_xor_sync(0xffffffffu, sc, 8);
        sc += __shfl_xor_sync(0xffffffffu, sc, 4);
        sc += __shfl_xor_sync(0xffffffffu, sc, 2);
        sc += __shfl_xor_sync(0xffffffffu, sc, 1);
        sc += mask[SPAST];
        float nm   = fmaxf(m, sc);
        float corr = __expf(m - nm);
        float p    = __expf(sc - nm);
        m = nm;
        l = l * corr + p;
        acc.x = acc.x * corr + p * v4.x;
        acc.y = acc.y * corr + p * v4.y;
        acc.z = acc.z * corr + p * v4.z;
        acc.w = acc.w * corr + p * v4.w;
    }

    // Combine the 8 warps of this block.
    __shared__ float  sm_m[8], sm_l[8];
    __shared__ float4 sm_acc[8][32];
    sm_acc[warp][lane] = acc;
    if (lane == 0) { sm_m[warp] = m; sm_l[warp] = l; }
    __syncthreads();

    if (threadIdx.x < HD_) {
        int d = threadIdx.x;
        float M = -1e30f;
#pragma unroll
        for (int w = 0; w < 8; w++) M = fmaxf(M, sm_m[w]);
        float L = 0.f, A = 0.f;
        const float* accf = (const float*)sm_acc;
#pragma unroll
        for (int w = 0; w < 8; w++) {
            float e = __expf(sm_m[w] - M);
            L += sm_l[w] * e;
            A += accf[w * HD_ + d] * e;
        }
        int idx = bh * SPLITS + split;
        g_pacc[idx * HD_ + d] = A;
        if (d == 0) { g_pm[idx] = M; g_pl[idx] = L; }
    }
}

// ---------------------------------------------------------------------------
// Combine the 8 split partials per (b,h) AND seed the final output buffer
// with the Wo bias, so the Wo split-K gemv can pure-atomicAdd.
// ---------------------------------------------------------------------------
__global__ __launch_bounds__(128) void attn_combine_kernel(
    float* __restrict__ out, const float* __restrict__ bo) {
    int bh = blockIdx.x;
    int d  = threadIdx.x;

    int oidx = bh * HD_ + d;          // [0, 32768)
    out[oidx] = bo[oidx & (D_ - 1)];  // seed Wo bias

    float M = -1e30f;
#pragma unroll
    for (int i = 0; i < SPLITS; i++) M = fmaxf(M, g_pm[bh * SPLITS + i]);
    float L = 0.f, A = 0.f;
#pragma unroll
    for (int i = 0; i < SPLITS; i++) {
        float e = __expf(g_pm[bh * SPLITS + i] - M);
        L += g_pl[bh * SPLITS + i] * e;
        A += g_pacc[(bh * SPLITS + i) * HD_ + d] * e;
    }
    int b = bh >> 4, h = bh & 15;
    g_attn[b * D_ + h * HD_ + d] = A / L;
}

// ---------------------------------------------------------------------------
extern "C" void kernel_launch(void* const* d_in, const int* in_sizes, int n_in,
                              void* d_out, int out_size) {
    const float* hs   = (const float*)d_in[0];
    const float* pk   = (const float*)d_in[1];
    const float* pv   = (const float*)d_in[2];
    const float* mask = (const float*)d_in[3];
    const float* Wq   = (const float*)d_in[4];
    const float* bq   = (const float*)d_in[5];
    const float* Wk   = (const float*)d_in[6];
    const float* bk   = (const float*)d_in[7];
    const float* Wv   = (const float*)d_in[8];
    const float* bv   = (const float*)d_in[9];
    const float* Wo   = (const float*)d_in[10];
    const float* bo   = (const float*)d_in[11];

    float* out  = (float*)d_out;          // [0, 32768): attn_output
    float* knew = out + B_ * D_;          // [32768, 65536): new_key
    float* vnew = out + 2 * B_ * D_;      // [65536, 98304): new_value

    float* qptr;  cudaGetSymbolAddress((void**)&qptr, g_q);
    float* aptr;  cudaGetSymbolAddress((void**)&aptr, g_attn);

    // 1. Fused QKV projection: 384 full-length blocks, direct bias store.
    GemvArgs a;
    a.W[0] = Wq; a.bias[0] = bq; a.out[0] = qptr; a.scale[0] = SCALING;
    a.W[1] = Wk; a.bias[1] = bk; a.out[1] = knew; a.scale[1] = 1.f;
    a.W[2] = Wv; a.bias[2] = bv; a.out[2] = vnew; a.scale[2] = 1.f;
    gemv_kernel<1><<<384, 128>>>(hs, a);

    // 2. Split-S attention partials (the HBM-bound 1.07 GB stream).
    attn_partial_kernel<<<dim3(B_ * H_, SPLITS), 256>>>(pk, pv, mask, knew, vnew);

    // 3. Combine partials + seed out with Wo bias.
    attn_combine_kernel<<<B_ * H_, 128>>>(out, bo);

    // 4. Output projection: split-K=4 -> 512 blocks, atomics into seeded out.
    GemvArgs ao;
    ao.W[0] = Wo; ao.bias[0] = bo; ao.out[0] = out; ao.scale[0] = 1.f;
    ao.W[1] = Wo; ao.bias[1] = bo; ao.out[1] = out; ao.scale[1] = 1.f;
    ao.W[2] = Wo; ao.bias[2] = bo; ao.out[2] = out; ao.scale[2] = 1.f;
    gemv_kernel<4><<<dim3(128, 4), 128>>>(aptr, ao);
}

// round 14
// speedup vs baseline: 1.1241x; 1.0014x over previous
#include <cuda_runtime.h>
#include <cstdint>
#include <math.h>

// Problem constants
constexpr int B_   = 16;
constexpr int H_   = 16;
constexpr int HD_  = 128;
constexpr int D_   = 2048;
constexpr int SPAST = 4096;
constexpr int SPLITS = 8;
constexpr int CHUNK  = 512;   // SPAST / SPLITS
constexpr float SCALING = 0.08838834764831845f;  // 128^-0.5

// Scratch (static device globals — no allocation allowed)
__device__ float g_q[B_ * D_];
__device__ float g_attn[B_ * D_];
__device__ float g_pm[B_ * H_ * SPLITS];
__device__ float g_pl[B_ * H_ * SPLITS];
__device__ float g_pacc[B_ * H_ * SPLITS * HD_];

struct GemvArgs {
    const float* W[3];
    const float* bias[3];
    float*       out[3];
    float        scale[3];
};

// ---------------------------------------------------------------------------
// r7 GEMV (the only config that ever measured fast) with ONE change: the
// 64-sum x 5-level SHFL warp reduction (~640 issue slots of 26-cycle
// dependent shuffles -- >50% of block time at small ITERS) is replaced by a
// padded-smem transpose reduction (~200 instrs, no long dependence chains).
// Geometry unchanged: 128 threads, 4 warps x 4 rows, depth-1 prefetch,
// KSPLIT=1 -> direct bias store; KSPLIT>1 -> atomicAdd into preseeded out.
// ---------------------------------------------------------------------------
template <int KSPLIT>
__global__ __launch_bounds__(128) void gemv_kernel(const float* __restrict__ x,
                                                   GemvArgs a) {
    __shared__ float sacc[256][33];   // 256 outputs x 32 lane-partials, pad 33

    int tid  = threadIdx.x;
    int warp = tid >> 5;
    int lane = tid & 31;
    int blk_row0 = blockIdx.x * 16;
    int mi   = blk_row0 >> 11;        // which matrix (2048 rows each)
    int o0b  = blk_row0 & 2047;       // block's first row within matrix
    int o0   = o0b + warp * 4;        // this warp's first row

    const float4* W = (const float4*)a.W[mi];
    const float4* X = (const float4*)x;

    float acc[4][16];
#pragma unroll
    for (int r = 0; r < 4; r++)
#pragma unroll
        for (int b = 0; b < 16; b++) acc[r][b] = 0.f;

    constexpr int ITERS = 16 / KSPLIT;
    int i0 = blockIdx.y * ITERS;

    // Depth-1 prefetch of the four weight rows.
    int d4 = i0 * 32 + lane;
    float4 w0 = __ldcs(&W[(size_t)(o0 + 0) * 512 + d4]);
    float4 w1 = __ldcs(&W[(size_t)(o0 + 1) * 512 + d4]);
    float4 w2 = __ldcs(&W[(size_t)(o0 + 2) * 512 + d4]);
    float4 w3 = __ldcs(&W[(size_t)(o0 + 3) * 512 + d4]);

#pragma unroll
    for (int ii = 0; ii < ITERS; ii++) {
        float4 c0 = w0, c1 = w1, c2 = w2, c3 = w3;
        int dcur = d4;
        if (ii + 1 < ITERS) {
            d4 += 32;
            w0 = __ldcs(&W[(size_t)(o0 + 0) * 512 + d4]);
            w1 = __ldcs(&W[(size_t)(o0 + 1) * 512 + d4]);
            w2 = __ldcs(&W[(size_t)(o0 + 2) * 512 + d4]);
            w3 = __ldcs(&W[(size_t)(o0 + 3) * 512 + d4]);
        }
#pragma unroll
        for (int b = 0; b < 16; b++) {
            float4 xv = X[b * 512 + dcur];
            acc[0][b] += c0.x * xv.x + c0.y * xv.y + c0.z * xv.z + c0.w * xv.w;
            acc[1][b] += c1.x * xv.x + c1.y * xv.y + c1.z * xv.z + c1.w * xv.w;
            acc[2][b] += c2.x * xv.x + c2.y * xv.y + c2.z * xv.z + c2.w * xv.w;
            acc[3][b] += c3.x * xv.x + c3.y * xv.y + c3.z * xv.z + c3.w * xv.w;
        }
    }

    // ---- smem transpose reduction (replaces 64 x 5-shfl butterflies) ----
    // Store: lane-partial of output (warp, r, b) at sacc[warp*64+r*16+b][lane]
    // (consecutive lanes -> consecutive words -> conflict-free).
#pragma unroll
    for (int r = 0; r < 4; r++)
#pragma unroll
        for (int b = 0; b < 16; b++)
            sacc[warp * 64 + r * 16 + b][lane] = acc[r][b];
    __syncthreads();

    // Read: thread t sums the 32 lane-partials of outputs t and t+128.
    // Word index = out*33 + l -> bank (out+l)%32: conflict-free.
    const float* bias = a.bias[mi];
    float*       out  = a.out[mi];
    float        sc   = a.scale[mi];
#pragma unroll
    for (int k = 0; k < 2; k++) {
        int oidx = tid + k * 128;               // [0, 256)
        int w2 = oidx >> 6;
        int r2 = (oidx >> 4) & 3;
        int b2 = oidx & 15;
        int row = o0b + w2 * 4 + r2;
        float sum = 0.f;
#pragma unroll
        for (int l = 0; l < 32; l++) sum += sacc[oidx][l];
        if (KSPLIT == 1)
            out[b2 * D_ + row] = (sum + bias[row]) * sc;
        else
            atomicAdd(&out[b2 * D_ + row], sum * sc);
    }
}

// ---------------------------------------------------------------------------
// Split-S flash-decode attention partials (proven structure, untouched).
// grid = (256 bh, 8 splits), block = 256 (8 warps). Warp-per-row online
// softmax; each lane owns 4 head-dim elements (float4).
// K/V are a 1 GB single-use stream: __ldcs keeps them out of L2's way.
// ---------------------------------------------------------------------------
__global__ __launch_bounds__(256) void attn_partial_kernel(
    const float* __restrict__ pk, const float* __restrict__ pv,
    const float* __restrict__ mask,
    const float* __restrict__ knew, const float* __restrict__ vnew) {
    int bh    = blockIdx.x;
    int split = blockIdx.y;
    int b     = bh >> 4;
    int h     = bh & 15;
    int warp  = threadIdx.x >> 5;
    int lane  = threadIdx.x & 31;

    const float4* q4p = (const float4*)(g_q + b * D_ + h * HD_);
    float4 q4 = q4p[lane];  // q pre-scaled by SCALING

    size_t base = ((size_t)b * SPAST) * D_ + h * HD_;

    float  m = -1e30f, l = 0.f;
    float4 acc = make_float4(0.f, 0.f, 0.f, 0.f);

    int s0 = split * CHUNK + warp;
    int s_end = split * CHUNK + CHUNK;

#pragma unroll 4
    for (int s = s0; s < s_end; s += 8) {
        const float4* kr = (const float4*)(pk + base + (size_t)s * D_);
        const float4* vr = (const float4*)(pv + base + (size_t)s * D_);
        float4 k4 = __ldcs(&kr[lane]);
        float4 v4 = __ldcs(&vr[lane]);
        float sc = k4.x * q4.x + k4.y * q4.y + k4.z * q4.z + k4.w * q4.w;
        sc += __shfl_xor_sync(0xffffffffu, sc, 16);
        sc += __shfl_xor_sync(0xffffffffu, sc, 8);
        sc += __shfl_xor_sync(0xffffffffu, sc, 4);
        sc += __shfl_xor_sync(0xffffffffu, sc, 2);
        sc += __shfl_xor_sync(0xffffffffu, sc, 1);
        sc += mask[s];
        float nm   = fmaxf(m, sc);
        float corr = __expf(m - nm);
        float p    = __expf(sc - nm);
        m = nm;
        l = l * corr + p;
        acc.x = acc.x * corr + p * v4.x;
        acc.y = acc.y * corr + p * v4.y;
        acc.z = acc.z * corr + p * v4.z;
        acc.w = acc.w * corr + p * v4.w;
    }

    // The new token (s = 4096) lives in the last split, handled by warp 0.
    if (split == SPLITS - 1 && warp == 0) {
        const float4* kr = (const float4*)(knew + b * D_ + h * HD_);
        const float4* vr = (const float4*)(vnew + b * D_ + h * HD_);
        float4 k4 = kr[lane];
        float4 v4 = vr[lane];
        float sc = k4.x * q4.x + k4.y * q4.y + k4.z * q4.z + k4.w * q4.w;
        sc += __shfl_xor_sync(0xffffffffu, sc, 16);
        sc += __shfl_xor_sync(0xffffffffu, sc, 8);
        sc += __shfl_xor_sync(0xffffffffu, sc, 4);
        sc += __shfl_xor_sync(0xffffffffu, sc, 2);
        sc += __shfl_xor_sync(0xffffffffu, sc, 1);
        sc += mask[SPAST];
        float nm   = fmaxf(m, sc);
        float corr = __expf(m - nm);
        float p    = __expf(sc - nm);
        m = nm;
        l = l * corr + p;
        acc.x = acc.x * corr + p * v4.x;
        acc.y = acc.y * corr + p * v4.y;
        acc.z = acc.z * corr + p * v4.z;
        acc.w = acc.w * corr + p * v4.w;
    }

    // Combine the 8 warps of this block.
    __shared__ float  sm_m[8], sm_l[8];
    __shared__ float4 sm_acc[8][32];
    sm_acc[warp][lane] = acc;
    if (lane == 0) { sm_m[warp] = m; sm_l[warp] = l; }
    __syncthreads();

    if (threadIdx.x < HD_) {
        int d = threadIdx.x;
        float M = -1e30f;
#pragma unroll
        for (int w = 0; w < 8; w++) M = fmaxf(M, sm_m[w]);
        float L = 0.f, A = 0.f;
        const float* accf = (const float*)sm_acc;
#pragma unroll
        for (int w = 0; w < 8; w++) {
            float e = __expf(sm_m[w] - M);
            L += sm_l[w] * e;
            A += accf[w * HD_ + d] * e;
        }
        int idx = bh * SPLITS + split;
        g_pacc[idx * HD_ + d] = A;
        if (d == 0) { g_pm[idx] = M; g_pl[idx] = L; }
    }
}

// ---------------------------------------------------------------------------
// Combine the 8 split partials per (b,h) AND seed the final output buffer
// with the Wo bias, so the Wo split-K gemv can pure-atomicAdd.
// ---------------------------------------------------------------------------
__global__ __launch_bounds__(128) void attn_combine_kernel(
    float* __restrict__ out, const float* __restrict__ bo) {
    int bh = blockIdx.x;
    int d  = threadIdx.x;

    int oidx = bh * HD_ + d;          // [0, 32768)
    out[oidx] = bo[oidx & (D_ - 1)];  // seed Wo bias

    float M = -1e30f;
#pragma unroll
    for (int i = 0; i < SPLITS; i++) M = fmaxf(M, g_pm[bh * SPLITS + i]);
    float L = 0.f, A = 0.f;
#pragma unroll
    for (int i = 0; i < SPLITS; i++) {
        float e = __expf(g_pm[bh * SPLITS + i] - M);
        L += g_pl[bh * SPLITS + i] * e;
        A += g_pacc[(bh * SPLITS + i) * HD_ + d] * e;
    }
    int b = bh >> 4, h = bh & 15;
    g_attn[b * D_ + h * HD_ + d] = A / L;
}

// ---------------------------------------------------------------------------
extern "C" void kernel_launch(void* const* d_in, const int* in_sizes, int n_in,
                              void* d_out, int out_size) {
    const float* hs   = (const float*)d_in[0];
    const float* pk   = (const float*)d_in[1];
    const float* pv   = (const float*)d_in[2];
    const float* mask = (const float*)d_in[3];
    const float* Wq   = (const float*)d_in[4];
    const float* bq   = (const float*)d_in[5];
    const float* Wk   = (const float*)d_in[6];
    const float* bk   = (const float*)d_in[7];
    const float* Wv   = (const float*)d_in[8];
    const float* bv   = (const float*)d_in[9];
    const float* Wo   = (const float*)d_in[10];
    const float* bo   = (const float*)d_in[11];

    float* out  = (float*)d_out;          // [0, 32768): attn_output
    float* knew = out + B_ * D_;          // [32768, 65536): new_key
    float* vnew = out + 2 * B_ * D_;      // [65536, 98304): new_value

    float* qptr;  cudaGetSymbolAddress((void**)&qptr, g_q);
    float* aptr;  cudaGetSymbolAddress((void**)&aptr, g_attn);

    // 1. Fused QKV projection: 384 full-length blocks, direct bias store.
    GemvArgs a;
    a.W[0] = Wq; a.bias[0] = bq; a.out[0] = qptr; a.scale[0] = SCALING;
    a.W[1] = Wk; a.bias[1] = bk; a.out[1] = knew; a.scale[1] = 1.f;
    a.W[2] = Wv; a.bias[2] = bv; a.out[2] = vnew; a.scale[2] = 1.f;
    gemv_kernel<1><<<384, 128>>>(hs, a);

    // 2. Split-S attention partials (the HBM-bound 1.07 GB stream).
    attn_partial_kernel<<<dim3(B_ * H_, SPLITS), 256>>>(pk, pv, mask, knew, vnew);

    // 3. Combine partials + seed out with Wo bias.
    attn_combine_kernel<<<B_ * H_, 128>>>(out, bo);

    // 4. Output projection: split-K=4 -> 512 blocks, atomics into seeded out.
    GemvArgs ao;
    ao.W[0] = Wo; ao.bias[0] = bo; ao.out[0] = out; ao.scale[0] = 1.f;
    ao.W[1] = Wo; ao.bias[1] = bo; ao.out[1] = out; ao.scale[1] = 1.f;
    ao.W[2] = Wo; ao.bias[2] = bo; ao.out[2] = out; ao.scale[2] = 1.f;
    gemv_kernel<4><<<dim3(128, 4), 128>>>(aptr, ao);
}